// round 16
// baseline (speedup 1.0000x reference)
#include <cuda_runtime.h>
#include <cuda_fp16.h>
#include <stdint.h>

#define NN 4096
#define SB 4

#define CSPLIT   4                    // column split factor
#define ROWS_PB  32                   // rows per block (4 warps x 8 rows)
#define RPW      8                    // rows per warp
#define COLS_PB  (NN / CSPLIT)        // 1024
#define NRG      (NN / ROWS_PB)       // 128 row-groups
#define ITERS    (COLS_PB / 128)      // 8 warp-steps of 128 contiguous cols
#define GRID     (NRG * CSPLIT)       // 512 blocks

// Scratch (allocation-free requirement => __device__ globals)
__device__ __align__(16) __half g_E [(size_t)NN * NN];   // exp(-C/eps)    [n][m]
__device__ __align__(16) __half g_Et[(size_t)NN * NN];   // transpose      [m][n]
__device__ __align__(16) float  g_u [SB * NN];
__device__ __align__(16) float  g_v [SB * NN];
__device__ __align__(16) float  g_part[CSPLIT * SB * NN]; // per-split partial sums
__device__ int g_cnt[NRG];                                // row-group arrival counters

// ---------------------------------------------------------------------------
// u0 = 1; counters = 0 (counters self-reset afterwards)
__global__ void init_u_kernel() {
    int i = blockIdx.x * blockDim.x + threadIdx.x;
    if (i < SB * NN) g_u[i] = 1.0f;
    if (i < NRG)     g_cnt[i] = 0;
}

// ---------------------------------------------------------------------------
// K = exp(-C/eps) in fp16 + transpose. C read with L2::evict_first so its
// 64 MB never displaces E/Et; E/Et written with L2::evict_last and stay
// L2-resident across the whole replay (proven in R13: DRAM fell to 4%).
__global__ __launch_bounds__(256) void prep_kernel(const float* __restrict__ C,
                                                   const float* __restrict__ eps_p) {
    __shared__ __half tile[32][33];
    unsigned long long polF, polL;
    asm("createpolicy.fractional.L2::evict_first.b64 %0, 1.0;" : "=l"(polF));
    asm("createpolicy.fractional.L2::evict_last.b64 %0, 1.0;"  : "=l"(polL));
    const float scale = -1.4426950408889634f / eps_p[0];
    const int tx = threadIdx.x, ty = threadIdx.y;
    const int x  = blockIdx.x * 32 + tx;
    const int yb = blockIdx.y * 32;
#pragma unroll
    for (int j = 0; j < 32; j += 8) {
        int y = yb + ty + j;
        float c;
        asm("ld.global.nc.L2::cache_hint.f32 %0, [%1], %2;"
            : "=f"(c) : "l"(C + (size_t)y * NN + x), "l"(polF));
        __half h = __float2half(exp2f(c * scale));
        unsigned short hb = __half_as_ushort(h);
        asm volatile("st.global.L2::cache_hint.b16 [%0], %1, %2;"
                     :: "l"(&g_E[(size_t)y * NN + x]), "h"(hb), "l"(polL) : "memory");
        tile[ty + j][tx] = h;
    }
    __syncthreads();
    const int x2  = blockIdx.y * 32 + tx;
    const int yb2 = blockIdx.x * 32;
#pragma unroll
    for (int j = 0; j < 32; j += 8) {
        unsigned short hb = __half_as_ushort(tile[tx][ty + j]);
        asm volatile("st.global.L2::cache_hint.b16 [%0], %1, %2;"
                     :: "l"(&g_Et[(size_t)(yb2 + ty + j) * NN + x2]), "h"(hb), "l"(polL) : "memory");
    }
}

// ---------------------------------------------------------------------------
// One Sinkhorn half-step:  xout[s][n] = ab[s][n] / sum_m M[n][m] * xin[s][m]
//
// rows/warp = 8 (u:E wavefront ratio 1:1 instead of 2:1 -> L1 port floor
// drops 1.5x), CSPLIT = 4 keeps grid at 512 / ~14 warps/SM. 64-reg f32x2
// accumulator block; __launch_bounds__(128,3) leaves a 170-reg budget so
// nothing spills and ptxas can batch loads. E loads: L1::no_allocate +
// L2::evict_last; u loads: v2.b64 (direct f32x2 operands), L1-hot.
__global__ __launch_bounds__(128, 3) void pass_kernel(int dir, const float* __restrict__ ab) {
    const __half* Mh   = dir ? g_Et : g_E;
    const float*  xin  = dir ? g_v  : g_u;
    float*        xout = dir ? g_u  : g_v;

    unsigned long long pol;
    asm("createpolicy.fractional.L2::evict_last.b64 %0, 1.0;" : "=l"(pol));

    const int rg   = blockIdx.x >> 2;      // row-group (0..127)
    const int q    = blockIdx.x & 3;       // column quarter
    const int warp = threadIdx.x >> 5;
    const int lane = threadIdx.x & 31;
    const int row0 = rg * ROWS_PB + warp * RPW;
    const int col0 = q * COLS_PB;

    unsigned long long acc[RPW][SB];
#pragma unroll
    for (int r = 0; r < RPW; r++)
#pragma unroll
        for (int s = 0; s < SB; s++) acc[r][s] = 0ull;

#pragma unroll 2
    for (int it = 0; it < ITERS; ++it) {
        const int ci = col0 + it * 128 + lane * 4;   // 4 contiguous cols per lane

        // u: 4 batches x 4 cols, loaded directly as packed f32x2 pairs
        unsigned long long u01[SB], u23[SB];
#pragma unroll
        for (int s = 0; s < SB; s++)
            asm("ld.global.nc.v2.b64 {%0,%1}, [%2];"
                : "=l"(u01[s]), "=l"(u23[s]) : "l"(xin + s * NN + ci));

#pragma unroll
        for (int r = 0; r < RPW; r++) {
            uint32_t ha, hb;   // 2x half2 = 4 E values for this row
            asm("ld.global.nc.L1::no_allocate.L2::cache_hint.v2.u32 {%0,%1}, [%2], %3;"
                : "=r"(ha), "=r"(hb)
                : "l"(Mh + (size_t)(row0 + r) * NN + ci), "l"(pol));
            float2 fa = __half22float2(*reinterpret_cast<const __half2*>(&ha));
            float2 fb = __half22float2(*reinterpret_cast<const __half2*>(&hb));
            unsigned long long e01, e23;
            asm("mov.b64 %0, {%1, %2};" : "=l"(e01) : "f"(fa.x), "f"(fa.y));
            asm("mov.b64 %0, {%1, %2};" : "=l"(e23) : "f"(fb.x), "f"(fb.y));
#pragma unroll
            for (int s = 0; s < SB; s++) {
                asm("fma.rn.f32x2 %0, %1, %2, %0;" : "+l"(acc[r][s]) : "l"(e01), "l"(u01[s]));
                asm("fma.rn.f32x2 %0, %1, %2, %0;" : "+l"(acc[r][s]) : "l"(e23), "l"(u23[s]));
            }
        }
    }

    // warp reduce each (row, batch); lane0 writes the partial for this quarter
#pragma unroll
    for (int r = 0; r < RPW; r++) {
#pragma unroll
        for (int s = 0; s < SB; s++) {
            float lo, hi;
            asm("mov.b64 {%0, %1}, %2;" : "=f"(lo), "=f"(hi) : "l"(acc[r][s]));
            float t = lo + hi;
#pragma unroll
            for (int o = 16; o; o >>= 1) t += __shfl_down_sync(0xffffffffu, t, o);
            if (lane == 0)
                g_part[(q * SB + s) * NN + row0 + r] = t;
        }
    }

    // last-block-per-row-group: deterministic fixed-order combine + divide
    __shared__ int s_last;
    __threadfence();
    __syncthreads();
    if (threadIdx.x == 0) {
        int old = atomicAdd(&g_cnt[rg], 1);
        s_last = (old == CSPLIT - 1);
    }
    __syncthreads();
    if (s_last) {
        __threadfence();
        {                                           // 128 outputs == blockDim
            int nl = threadIdx.x >> 2;              // row within group (0..31)
            int s  = threadIdx.x & 3;               // batch
            int n  = rg * ROWS_PB + nl;
            float t = 0.0f;
#pragma unroll
            for (int qq = 0; qq < CSPLIT; qq++)     // fixed order => deterministic
                t += __ldcv(&g_part[(qq * SB + s) * NN + n]);
            xout[s * NN + n] = __ldg(&ab[s * NN + n]) / t;
        }
        if (threadIdx.x == 0) g_cnt[rg] = 0;        // self-clean for next pass
    }
}

// ---------------------------------------------------------------------------
// f = eps*log(v), g = eps*log(u)
__global__ void final_kernel(float* __restrict__ out, const float* __restrict__ eps_p) {
    int i = blockIdx.x * blockDim.x + threadIdx.x;
    float eps = eps_p[0];
    if (i < SB * NN) {
        out[i]           = eps * __logf(g_v[i]);  // f
        out[SB * NN + i] = eps * __logf(g_u[i]);  // g
    }
}

// ---------------------------------------------------------------------------
extern "C" void kernel_launch(void* const* d_in, const int* in_sizes, int n_in,
                              void* d_out, int out_size) {
    const float* alpha = (const float*)d_in[0];  // (4, 4096)
    const float* beta  = (const float*)d_in[1];  // (4, 4096)
    const float* C     = (const float*)d_in[2];  // (4096, 4096)
    const float* eps   = (const float*)d_in[3];  // scalar
    float* out = (float*)d_out;                  // f then g

    init_u_kernel<<<(SB * NN + 255) / 256, 256>>>();

    dim3 pb(32, 8), pg(NN / 32, NN / 32);
    prep_kernel<<<pg, pb>>>(C, eps);

    for (int it = 0; it < 10; it++) {
        pass_kernel<<<GRID, 128>>>(0, alpha);  // v = alpha / (K  u)
        pass_kernel<<<GRID, 128>>>(1, beta);   // u = beta  / (K^T v)
    }

    final_kernel<<<(SB * NN + 255) / 256, 256>>>(out, eps);
}